// round 1
// baseline (speedup 1.0000x reference)
#include <cuda_runtime.h>
#include <math.h>

// ---------------------------------------------------------------------------
// Mamba block forward, fp32.
//   B=2, L=2048, d_model=1024, d_inner=2048, d_state=16, d_conv=4, dt_rank=64
// Pipeline:
//   1. sgemm_tn : xz = x @ W_in^T                      (4096 x 4096, K=1024)
//   2. conv_silu: u_c = silu(depthwise_causal_conv(u))
//   3. sgemm_tn (split-K x8) + reduce: x_dbl = u_c @ W_xproj^T (4096 x 96)
//   4. sgemm_tn : delta = softplus(dt @ W_dtproj^T + dt_bias)  (4096 x 2048)
//   5. scan_k   : selective scan + skip(D) + gate(silu(z))
//   6. sgemm_tn : out = y @ W_out^T                    (4096 x 1024, K=2048)
// ---------------------------------------------------------------------------

#define L_SEQ   2048
#define NB      2
#define DMODEL  1024
#define DINNER  2048
#define DSTATE  16
#define NROWS   (NB * L_SEQ)     // 4096
#define XPROJ_N 96
#define KSPLIT  8

// Scratch (module-load allocated, legal under the no-alloc rule)
__device__ float g_xz   [(size_t)NROWS * 2 * DINNER];   // 64 MB  (u | z)
__device__ float g_uc   [(size_t)NROWS * DINNER];       // 32 MB
__device__ float g_xpart[(size_t)KSPLIT * NROWS * XPROJ_N];
__device__ float g_xdbl [(size_t)NROWS * XPROJ_N];
__device__ float g_delta[(size_t)NROWS * DINNER];       // 32 MB
__device__ float g_y    [(size_t)NROWS * DINNER];       // 32 MB

__device__ __forceinline__ float softplusf(float x) {
    return x > 20.f ? x : log1pf(__expf(x));
}

// ---------------------------------------------------------------------------
// C[M,N] (+= over split-K slices) = A[M,K] @ B[N,K]^T   (both K-contiguous)
// 128x128 tile, BK=16, 256 threads, 8x8 per thread (2x2 of 4x4 quadrants).
// epi==1: C = softplus(C + bias[n]) fused epilogue.
// Split-K: blockIdx.z selects K range [z*kPerSplit, ...), writes slice z of C.
// ---------------------------------------------------------------------------
__global__ __launch_bounds__(256)
void sgemm_tn(const float* __restrict__ A, const float* __restrict__ B,
              float* __restrict__ C, int M, int N, int K,
              int lda, int ldb, int ldc,
              const float* __restrict__ bias, int epi, int kPerSplit)
{
    __shared__ __align__(16) float As[16][128];
    __shared__ __align__(16) float Bs[16][128];

    const int tid = threadIdx.x;
    const int tx = tid & 15, ty = tid >> 4;
    const int bm = blockIdx.y << 7, bn = blockIdx.x << 7;
    const int kbeg = blockIdx.z * kPerSplit;
    const int kend = min(K, kbeg + kPerSplit);
    C += (size_t)blockIdx.z * (size_t)M * (size_t)ldc;

    float acc[8][8];
#pragma unroll
    for (int i = 0; i < 8; ++i)
#pragma unroll
        for (int j = 0; j < 8; ++j) acc[i][j] = 0.f;

    const int r0 = tid >> 2;        // 0..63
    const int kq = (tid & 3) << 2;  // 0,4,8,12

    for (int k0 = kbeg; k0 < kend; k0 += 16) {
        __syncthreads();
#pragma unroll
        for (int i = 0; i < 2; ++i) {
            int r = r0 + (i << 6);
            float4 va = *reinterpret_cast<const float4*>(
                A + (size_t)(bm + r) * lda + k0 + kq);
            As[kq + 0][r] = va.x; As[kq + 1][r] = va.y;
            As[kq + 2][r] = va.z; As[kq + 3][r] = va.w;
            float4 vb = make_float4(0.f, 0.f, 0.f, 0.f);
            if (bn + r < N)
                vb = *reinterpret_cast<const float4*>(
                    B + (size_t)(bn + r) * ldb + k0 + kq);
            Bs[kq + 0][r] = vb.x; Bs[kq + 1][r] = vb.y;
            Bs[kq + 2][r] = vb.z; Bs[kq + 3][r] = vb.w;
        }
        __syncthreads();
#pragma unroll
        for (int k = 0; k < 16; ++k) {
            float a[8], b[8];
            float4 t0 = *reinterpret_cast<const float4*>(&As[k][ty * 4]);
            float4 t1 = *reinterpret_cast<const float4*>(&As[k][64 + ty * 4]);
            a[0]=t0.x; a[1]=t0.y; a[2]=t0.z; a[3]=t0.w;
            a[4]=t1.x; a[5]=t1.y; a[6]=t1.z; a[7]=t1.w;
            float4 s0 = *reinterpret_cast<const float4*>(&Bs[k][tx * 4]);
            float4 s1 = *reinterpret_cast<const float4*>(&Bs[k][64 + tx * 4]);
            b[0]=s0.x; b[1]=s0.y; b[2]=s0.z; b[3]=s0.w;
            b[4]=s1.x; b[5]=s1.y; b[6]=s1.z; b[7]=s1.w;
#pragma unroll
            for (int i = 0; i < 8; ++i)
#pragma unroll
                for (int j = 0; j < 8; ++j)
                    acc[i][j] = fmaf(a[i], b[j], acc[i][j]);
        }
    }

#pragma unroll
    for (int ih = 0; ih < 2; ++ih)
#pragma unroll
        for (int i = 0; i < 4; ++i) {
            int r = bm + (ih << 6) + ty * 4 + i;
#pragma unroll
            for (int jh = 0; jh < 2; ++jh) {
                int c = bn + (jh << 6) + tx * 4;
                if (c < N) {   // N % 4 == 0 in all uses
                    float v0 = acc[ih * 4 + i][jh * 4 + 0];
                    float v1 = acc[ih * 4 + i][jh * 4 + 1];
                    float v2 = acc[ih * 4 + i][jh * 4 + 2];
                    float v3 = acc[ih * 4 + i][jh * 4 + 3];
                    if (epi == 1) {
                        v0 = softplusf(v0 + bias[c + 0]);
                        v1 = softplusf(v1 + bias[c + 1]);
                        v2 = softplusf(v2 + bias[c + 2]);
                        v3 = softplusf(v3 + bias[c + 3]);
                    }
                    *reinterpret_cast<float4*>(C + (size_t)r * ldc + c) =
                        make_float4(v0, v1, v2, v3);
                }
            }
        }
}

// ---------------------------------------------------------------------------
// Depthwise causal conv (width 4) + bias + SiLU, over the u half of xz.
// ---------------------------------------------------------------------------
__global__ __launch_bounds__(256)
void conv_silu_k(const float* __restrict__ xz, const float* __restrict__ w,
                 const float* __restrict__ cb, float* __restrict__ uc)
{
    int idx = blockIdx.x * blockDim.x + threadIdx.x;
    if (idx >= NROWS * DINNER) return;
    int d   = idx & (DINNER - 1);
    int row = idx >> 11;           // DINNER = 2048
    int l   = row & (L_SEQ - 1);
    int b   = row >> 11;           // L_SEQ = 2048

    const float4 wv = *reinterpret_cast<const float4*>(w + (size_t)d * 4);
    const float* up = xz + (size_t)b * L_SEQ * (2 * DINNER) + d;
    const size_t S = 2 * DINNER;

    float acc = cb[d] + wv.w * up[(size_t)l * S];
    if (l >= 1) acc += wv.z * up[(size_t)(l - 1) * S];
    if (l >= 2) acc += wv.y * up[(size_t)(l - 2) * S];
    if (l >= 3) acc += wv.x * up[(size_t)(l - 3) * S];

    uc[idx] = acc / (1.f + __expf(-acc));   // silu
}

// ---------------------------------------------------------------------------
// Reduce the KSPLIT partial sums of the x_proj GEMM.
// ---------------------------------------------------------------------------
__global__ void reduce_split(const float* __restrict__ part,
                             float* __restrict__ out, int n)
{
    int i = blockIdx.x * blockDim.x + threadIdx.x;
    if (i < n) {
        float s = 0.f;
#pragma unroll
        for (int z = 0; z < KSPLIT; ++z) s += part[(size_t)z * n + i];
        out[i] = s;
    }
}

// ---------------------------------------------------------------------------
// Selective scan: one thread per (b, d) channel, h[16] in registers,
// sequential over L. B/C rows staged through shared in tiles of 32 steps.
// Fuses skip (D*u) and gate (silu(z)) into the output.
// ---------------------------------------------------------------------------
__global__ __launch_bounds__(256)
void scan_k(const float* __restrict__ delta, const float* __restrict__ xdbl,
            const float* __restrict__ uc, const float* __restrict__ xz,
            const float* __restrict__ A_log, const float* __restrict__ Dv,
            float* __restrict__ y)
{
    const int b = blockIdx.y;
    const int d = blockIdx.x * 256 + threadIdx.x;

    float na[DSTATE];
#pragma unroll
    for (int s = 0; s < DSTATE; ++s)
        na[s] = -__expf(A_log[(size_t)d * DSTATE + s]);   // A[d,s]

    float h[DSTATE];
#pragma unroll
    for (int s = 0; s < DSTATE; ++s) h[s] = 0.f;

    const float Dd = Dv[d];
    __shared__ float bc[32][32];   // [step-in-tile][B(16) | C(16)]

    for (int l0 = 0; l0 < L_SEQ; l0 += 32) {
        __syncthreads();
        for (int t = threadIdx.x; t < 1024; t += 256) {
            int i = t >> 5, j = t & 31;
            bc[i][j] = xdbl[(size_t)(b * L_SEQ + l0 + i) * XPROJ_N + 64 + j];
        }
        __syncthreads();
#pragma unroll 4
        for (int i = 0; i < 32; ++i) {
            size_t row = (size_t)b * L_SEQ + l0 + i;
            float t  = delta[row * DINNER + d];
            float u  = uc[row * DINNER + d];
            float tu = t * u;
            float yv = 0.f;
#pragma unroll
            for (int s = 0; s < DSTATE; ++s) {
                float dA = __expf(t * na[s]);
                h[s] = fmaf(dA, h[s], tu * bc[i][s]);
                yv   = fmaf(h[s], bc[i][16 + s], yv);
            }
            float zv = xz[row * (2 * DINNER) + DINNER + d];
            float g  = zv / (1.f + __expf(-zv));           // silu(z)
            y[row * DINNER + d] = (yv + u * Dd) * g;
        }
    }
}

// ---------------------------------------------------------------------------
extern "C" void kernel_launch(void* const* d_in, const int* in_sizes, int n_in,
                              void* d_out, int out_size)
{
    const float* x        = (const float*)d_in[0];
    const float* W_in     = (const float*)d_in[1];
    const float* conv_w   = (const float*)d_in[2];
    const float* conv_b   = (const float*)d_in[3];
    const float* W_xproj  = (const float*)d_in[4];
    const float* W_dtproj = (const float*)d_in[5];
    const float* dt_bias  = (const float*)d_in[6];
    const float* A_log    = (const float*)d_in[7];
    const float* Dv       = (const float*)d_in[8];
    const float* W_out    = (const float*)d_in[9];
    float* out = (float*)d_out;

    float *xz, *uc, *xpart, *xdbl, *delta, *y;
    cudaGetSymbolAddress((void**)&xz,    g_xz);
    cudaGetSymbolAddress((void**)&uc,    g_uc);
    cudaGetSymbolAddress((void**)&xpart, g_xpart);
    cudaGetSymbolAddress((void**)&xdbl,  g_xdbl);
    cudaGetSymbolAddress((void**)&delta, g_delta);
    cudaGetSymbolAddress((void**)&y,     g_y);

    dim3 blk(256);

    // 1. in_proj: xz[4096,4096] = x @ W_in^T
    sgemm_tn<<<dim3(32, 32, 1), blk>>>(x, W_in, xz,
        NROWS, 2 * DINNER, DMODEL, DMODEL, DMODEL, 2 * DINNER,
        nullptr, 0, DMODEL);

    // 2. depthwise conv + silu
    conv_silu_k<<<(NROWS * DINNER) / 256, blk>>>(xz, conv_w, conv_b, uc);

    // 3. x_proj (split-K x8): x_dbl[4096,96] = u_c @ W_xproj^T
    sgemm_tn<<<dim3(1, 32, KSPLIT), blk>>>(uc, W_xproj, xpart,
        NROWS, XPROJ_N, DINNER, DINNER, DINNER, XPROJ_N,
        nullptr, 0, DINNER / KSPLIT);
    reduce_split<<<(NROWS * XPROJ_N + 255) / 256, blk>>>(
        xpart, xdbl, NROWS * XPROJ_N);

    // 4. dt_proj + softplus: delta[4096,2048]
    sgemm_tn<<<dim3(16, 32, 1), blk>>>(xdbl, W_dtproj, delta,
        NROWS, DINNER, 64, XPROJ_N, 64, DINNER,
        dt_bias, 1, 64);

    // 5. selective scan + skip + gate
    scan_k<<<dim3(DINNER / 256, NB), blk>>>(delta, xdbl, uc, xz, A_log, Dv, y);

    // 6. out_proj: out[4096,1024] = y @ W_out^T
    sgemm_tn<<<dim3(8, 32, 1), blk>>>(y, W_out, out,
        NROWS, DMODEL, DINNER, DINNER, DINNER, DMODEL,
        nullptr, 0, DINNER);
}

// round 2
// speedup vs baseline: 1.3632x; 1.3632x over previous
#include <cuda_runtime.h>
#include <math.h>

// ---------------------------------------------------------------------------
// Mamba block forward.  GEMMs on tensor pipe via mma.sync tf32.
//   B=2, L=2048, d_model=1024, d_inner=2048, d_state=16, d_conv=4, dt_rank=64
// ---------------------------------------------------------------------------

#define L_SEQ   2048
#define NB      2
#define DMODEL  1024
#define DINNER  2048
#define DSTATE  16
#define NROWS   (NB * L_SEQ)     // 4096
#define XPROJ_N 96
#define KSPLIT  8

__device__ float g_xz   [(size_t)NROWS * 2 * DINNER];
__device__ float g_uc   [(size_t)NROWS * DINNER];
__device__ float g_xpart[(size_t)KSPLIT * NROWS * XPROJ_N];
__device__ float g_xdbl [(size_t)NROWS * XPROJ_N];
__device__ float g_delta[(size_t)NROWS * DINNER];
__device__ float g_y    [(size_t)NROWS * DINNER];

__device__ __forceinline__ float softplusf(float x) {
    return x > 20.f ? x : log1pf(__expf(x));
}
__device__ __forceinline__ unsigned f2tf32(float f) {
    unsigned u;
    asm("cvt.rna.tf32.f32 %0, %1;" : "=r"(u) : "f"(f));
    return u;
}
__device__ __forceinline__ unsigned smem_u32(const void* p) {
    return (unsigned)__cvta_generic_to_shared(p);
}

// ---------------------------------------------------------------------------
// C[M,N] = A[M,K] @ B[N,K]^T via mma.sync.m16n8k8.tf32.
// 128x128 block tile, BK=32, 256 threads = 8 warps (4m x 2n), warp = 32m x 64n.
// epi==1: C = softplus(C + bias[n]).  Split-K via blockIdx.z (slice output).
// ---------------------------------------------------------------------------
#define BK   32
#define BST  36   // BK + 4 pad (ldmatrix conflict-free)

__global__ __launch_bounds__(256)
void mma_tn(const float* __restrict__ A, const float* __restrict__ B,
            float* __restrict__ C, int M, int N, int K,
            int lda, int ldb, int ldc,
            const float* __restrict__ bias, int epi, int kPerSplit)
{
    __shared__ __align__(16) unsigned As[128 * BST];
    __shared__ __align__(16) unsigned Bs[128 * BST];

    const int tid  = threadIdx.x;
    const int lane = tid & 31;
    const int wid  = tid >> 5;
    const int wm0  = (wid >> 1) << 5;   // warp m offset: 0,32,64,96
    const int wn0  = (wid & 1) << 6;    // warp n offset: 0,64

    const int bm = blockIdx.y << 7;
    const int bn = blockIdx.x << 7;
    const int kbeg = blockIdx.z * kPerSplit;
    const int kend = kbeg + kPerSplit;
    C += (size_t)blockIdx.z * (size_t)M * (size_t)ldc;

    float acc[2][8][4];
#pragma unroll
    for (int mt = 0; mt < 2; ++mt)
#pragma unroll
        for (int nt = 0; nt < 8; ++nt)
#pragma unroll
            for (int r = 0; r < 4; ++r) acc[mt][nt][r] = 0.f;

    // ldmatrix per-lane source offsets (in floats, col part added per k-step)
    // A x4 tile (16m x 8k): groups g0 rows m..m+7 k, g1 m+8.. k, g2 m.. k+4, g3 m+8.. k+4
    int a_off[2], b_off[4];
#pragma unroll
    for (int mt = 0; mt < 2; ++mt) {
        int row = wm0 + mt * 16 + ((lane >> 3) & 1) * 8 + (lane & 7);
        int col = (lane >> 4) * 4;
        a_off[mt] = row * BST + col;
    }
    // B x4 tile (16n x 8k): g0 n..n+7 k, g1 n..n+7 k+4, g2 n+8.. k, g3 n+8.. k+4
#pragma unroll
    for (int bt = 0; bt < 4; ++bt) {
        int row = wn0 + bt * 16 + (lane >> 4) * 8 + (lane & 7);
        int col = ((lane >> 3) & 1) * 4;
        b_off[bt] = row * BST + col;
    }
    const unsigned as_base = smem_u32(As);
    const unsigned bs_base = smem_u32(Bs);

    const int lrow = tid >> 3;          // 0..31
    const int lc4  = (tid & 7) << 2;    // 0,4,...,28

    for (int k0 = kbeg; k0 < kend; k0 += BK) {
#pragma unroll
        for (int i = 0; i < 4; ++i) {
            int r = lrow + (i << 5);
            float4 va = *reinterpret_cast<const float4*>(
                A + (size_t)(bm + r) * lda + k0 + lc4);
            unsigned* pa = &As[r * BST + lc4];
            pa[0] = f2tf32(va.x); pa[1] = f2tf32(va.y);
            pa[2] = f2tf32(va.z); pa[3] = f2tf32(va.w);
            float4 vb = make_float4(0.f, 0.f, 0.f, 0.f);
            if (bn + r < N)
                vb = *reinterpret_cast<const float4*>(
                    B + (size_t)(bn + r) * ldb + k0 + lc4);
            unsigned* pb = &Bs[r * BST + lc4];
            pb[0] = f2tf32(vb.x); pb[1] = f2tf32(vb.y);
            pb[2] = f2tf32(vb.z); pb[3] = f2tf32(vb.w);
        }
        __syncthreads();

#pragma unroll
        for (int kk = 0; kk < BK; kk += 8) {
            unsigned a[2][4], b[4][4];
#pragma unroll
            for (int mt = 0; mt < 2; ++mt) {
                unsigned addr = as_base + (unsigned)((a_off[mt] + kk) << 2);
                asm volatile(
                    "ldmatrix.sync.aligned.m8n8.x4.shared.b16 {%0,%1,%2,%3}, [%4];"
                    : "=r"(a[mt][0]), "=r"(a[mt][1]), "=r"(a[mt][2]), "=r"(a[mt][3])
                    : "r"(addr));
            }
#pragma unroll
            for (int bt = 0; bt < 4; ++bt) {
                unsigned addr = bs_base + (unsigned)((b_off[bt] + kk) << 2);
                asm volatile(
                    "ldmatrix.sync.aligned.m8n8.x4.shared.b16 {%0,%1,%2,%3}, [%4];"
                    : "=r"(b[bt][0]), "=r"(b[bt][1]), "=r"(b[bt][2]), "=r"(b[bt][3])
                    : "r"(addr));
            }
#pragma unroll
            for (int mt = 0; mt < 2; ++mt)
#pragma unroll
                for (int nt = 0; nt < 8; ++nt) {
                    unsigned b0 = b[nt >> 1][(nt & 1) * 2 + 0];
                    unsigned b1 = b[nt >> 1][(nt & 1) * 2 + 1];
                    asm volatile(
                        "mma.sync.aligned.m16n8k8.row.col.f32.tf32.tf32.f32 "
                        "{%0,%1,%2,%3}, {%4,%5,%6,%7}, {%8,%9}, {%0,%1,%2,%3};"
                        : "+f"(acc[mt][nt][0]), "+f"(acc[mt][nt][1]),
                          "+f"(acc[mt][nt][2]), "+f"(acc[mt][nt][3])
                        : "r"(a[mt][0]), "r"(a[mt][1]), "r"(a[mt][2]), "r"(a[mt][3]),
                          "r"(b0), "r"(b1));
                }
        }
        __syncthreads();
    }

    // Epilogue: c0,c1 at (m = g, n = 2*t), c2,c3 at (m+8, same n)
    const int gid = lane >> 2;
    const int tig = lane & 3;
#pragma unroll
    for (int mt = 0; mt < 2; ++mt)
#pragma unroll
        for (int nt = 0; nt < 8; ++nt) {
            int m = bm + wm0 + mt * 16 + gid;
            int n = bn + wn0 + nt * 8 + tig * 2;
            if (n < N) {
                float v0 = acc[mt][nt][0], v1 = acc[mt][nt][1];
                float v2 = acc[mt][nt][2], v3 = acc[mt][nt][3];
                if (epi == 1) {
                    float b0v = bias[n], b1v = bias[n + 1];
                    v0 = softplusf(v0 + b0v); v1 = softplusf(v1 + b1v);
                    v2 = softplusf(v2 + b0v); v3 = softplusf(v3 + b1v);
                }
                *reinterpret_cast<float2*>(C + (size_t)m * ldc + n) =
                    make_float2(v0, v1);
                *reinterpret_cast<float2*>(C + (size_t)(m + 8) * ldc + n) =
                    make_float2(v2, v3);
            }
        }
}

// ---------------------------------------------------------------------------
__global__ __launch_bounds__(256)
void conv_silu_k(const float* __restrict__ xz, const float* __restrict__ w,
                 const float* __restrict__ cb, float* __restrict__ uc)
{
    int idx = blockIdx.x * blockDim.x + threadIdx.x;
    if (idx >= NROWS * DINNER) return;
    int d   = idx & (DINNER - 1);
    int row = idx >> 11;
    int l   = row & (L_SEQ - 1);
    int b   = row >> 11;

    const float4 wv = *reinterpret_cast<const float4*>(w + (size_t)d * 4);
    const float* up = xz + (size_t)b * L_SEQ * (2 * DINNER) + d;
    const size_t S = 2 * DINNER;

    float acc = cb[d] + wv.w * up[(size_t)l * S];
    if (l >= 1) acc += wv.z * up[(size_t)(l - 1) * S];
    if (l >= 2) acc += wv.y * up[(size_t)(l - 2) * S];
    if (l >= 3) acc += wv.x * up[(size_t)(l - 3) * S];

    uc[idx] = acc / (1.f + __expf(-acc));
}

__global__ void reduce_split(const float* __restrict__ part,
                             float* __restrict__ out, int n)
{
    int i = blockIdx.x * blockDim.x + threadIdx.x;
    if (i < n) {
        float s = 0.f;
#pragma unroll
        for (int z = 0; z < KSPLIT; ++z) s += part[(size_t)z * n + i];
        out[i] = s;
    }
}

// ---------------------------------------------------------------------------
__global__ __launch_bounds__(256)
void scan_k(const float* __restrict__ delta, const float* __restrict__ xdbl,
            const float* __restrict__ uc, const float* __restrict__ xz,
            const float* __restrict__ A_log, const float* __restrict__ Dv,
            float* __restrict__ y)
{
    const int b = blockIdx.y;
    const int d = blockIdx.x * 256 + threadIdx.x;

    float na[DSTATE];
#pragma unroll
    for (int s = 0; s < DSTATE; ++s)
        na[s] = -__expf(A_log[(size_t)d * DSTATE + s]);

    float h[DSTATE];
#pragma unroll
    for (int s = 0; s < DSTATE; ++s) h[s] = 0.f;

    const float Dd = Dv[d];
    __shared__ float bc[32][32];

    for (int l0 = 0; l0 < L_SEQ; l0 += 32) {
        __syncthreads();
        for (int t = threadIdx.x; t < 1024; t += 256) {
            int i = t >> 5, j = t & 31;
            bc[i][j] = xdbl[(size_t)(b * L_SEQ + l0 + i) * XPROJ_N + 64 + j];
        }
        __syncthreads();
#pragma unroll 4
        for (int i = 0; i < 32; ++i) {
            size_t row = (size_t)b * L_SEQ + l0 + i;
            float t  = delta[row * DINNER + d];
            float u  = uc[row * DINNER + d];
            float tu = t * u;
            float yv = 0.f;
#pragma unroll
            for (int s = 0; s < DSTATE; ++s) {
                float dA = __expf(t * na[s]);
                h[s] = fmaf(dA, h[s], tu * bc[i][s]);
                yv   = fmaf(h[s], bc[i][16 + s], yv);
            }
            float zv = xz[row * (2 * DINNER) + DINNER + d];
            float g  = zv / (1.f + __expf(-zv));
            y[row * DINNER + d] = (yv + u * Dd) * g;
        }
    }
}

// ---------------------------------------------------------------------------
extern "C" void kernel_launch(void* const* d_in, const int* in_sizes, int n_in,
                              void* d_out, int out_size)
{
    const float* x        = (const float*)d_in[0];
    const float* W_in     = (const float*)d_in[1];
    const float* conv_w   = (const float*)d_in[2];
    const float* conv_b   = (const float*)d_in[3];
    const float* W_xproj  = (const float*)d_in[4];
    const float* W_dtproj = (const float*)d_in[5];
    const float* dt_bias  = (const float*)d_in[6];
    const float* A_log    = (const float*)d_in[7];
    const float* Dv       = (const float*)d_in[8];
    const float* W_out    = (const float*)d_in[9];
    float* out = (float*)d_out;

    float *xz, *uc, *xpart, *xdbl, *delta, *y;
    cudaGetSymbolAddress((void**)&xz,    g_xz);
    cudaGetSymbolAddress((void**)&uc,    g_uc);
    cudaGetSymbolAddress((void**)&xpart, g_xpart);
    cudaGetSymbolAddress((void**)&xdbl,  g_xdbl);
    cudaGetSymbolAddress((void**)&delta, g_delta);
    cudaGetSymbolAddress((void**)&y,     g_y);

    dim3 blk(256);

    // 1. in_proj: xz[4096,4096] = x @ W_in^T  (K=1024)
    mma_tn<<<dim3(32, 32, 1), blk>>>(x, W_in, xz,
        NROWS, 2 * DINNER, DMODEL, DMODEL, DMODEL, 2 * DINNER,
        nullptr, 0, DMODEL);

    // 2. depthwise conv + silu
    conv_silu_k<<<(NROWS * DINNER) / 256, blk>>>(xz, conv_w, conv_b, uc);

    // 3. x_proj (split-K x8): x_dbl[4096,96] = u_c @ W_xproj^T (K=2048)
    mma_tn<<<dim3(1, 32, KSPLIT), blk>>>(uc, W_xproj, xpart,
        NROWS, XPROJ_N, DINNER, DINNER, DINNER, XPROJ_N,
        nullptr, 0, DINNER / KSPLIT);
    reduce_split<<<(NROWS * XPROJ_N + 255) / 256, blk>>>(
        xpart, xdbl, NROWS * XPROJ_N);

    // 4. dt_proj + softplus: delta[4096,2048] (K=64)
    mma_tn<<<dim3(16, 32, 1), blk>>>(xdbl, W_dtproj, delta,
        NROWS, DINNER, 64, XPROJ_N, 64, DINNER,
        dt_bias, 1, 64);

    // 5. selective scan + skip + gate
    scan_k<<<dim3(DINNER / 256, NB), blk>>>(delta, xdbl, uc, xz, A_log, Dv, y);

    // 6. out_proj: out[4096,1024] = y @ W_out^T (K=2048)
    mma_tn<<<dim3(8, 32, 1), blk>>>(y, W_out, out,
        NROWS, DMODEL, DINNER, DINNER, DINNER, DMODEL,
        nullptr, 0, DINNER);
}

// round 3
// speedup vs baseline: 4.7033x; 3.4501x over previous
#include <cuda_runtime.h>
#include <math.h>

// ---------------------------------------------------------------------------
// Mamba block forward. tf32 mma.sync GEMMs + chunked parallel selective scan.
//   B=2, L=2048, d_model=1024, d_inner=2048, d_state=16, d_conv=4, dt_rank=64
// ---------------------------------------------------------------------------

#define L_SEQ   2048
#define NB      2
#define DMODEL  1024
#define DINNER  2048
#define DSTATE  16
#define NROWS   (NB * L_SEQ)     // 4096
#define XPROJ_N 96
#define KSPLIT  8
#define CHUNK   128
#define NCHUNK  (L_SEQ / CHUNK)  // 16

__device__ float g_xz   [(size_t)NROWS * 2 * DINNER];
__device__ float g_uc   [(size_t)NROWS * DINNER];
__device__ float g_xpart[(size_t)KSPLIT * NROWS * XPROJ_N];
__device__ float g_xdbl [(size_t)NROWS * XPROJ_N];
__device__ float g_delta[(size_t)NROWS * DINNER];
__device__ float g_y    [(size_t)NROWS * DINNER];
// chunk summaries / initial states: [b][chunk][s][d]
__device__ float g_hfin [(size_t)NB * NCHUNK * DSTATE * DINNER];
__device__ float g_hini [(size_t)NB * NCHUNK * DSTATE * DINNER];
__device__ float g_sumd [(size_t)NB * NCHUNK * DINNER];

__device__ __forceinline__ float softplusf(float x) {
    return x > 20.f ? x : log1pf(__expf(x));
}
__device__ __forceinline__ unsigned f2tf32(float f) {
    unsigned u;
    asm("cvt.rna.tf32.f32 %0, %1;" : "=r"(u) : "f"(f));
    return u;
}
__device__ __forceinline__ unsigned smem_u32(const void* p) {
    return (unsigned)__cvta_generic_to_shared(p);
}

// ---------------------------------------------------------------------------
// C[M,N] = A[M,K] @ B[N,K]^T via mma.sync.m16n8k8.tf32.
// 128x128 block tile, BK=32, 256 threads = 8 warps (4m x 2n), warp = 32m x 64n.
// ---------------------------------------------------------------------------
#define BK   32
#define BST  36

__global__ __launch_bounds__(256)
void mma_tn(const float* __restrict__ A, const float* __restrict__ B,
            float* __restrict__ C, int M, int N, int K,
            int lda, int ldb, int ldc,
            const float* __restrict__ bias, int epi, int kPerSplit)
{
    __shared__ __align__(16) unsigned As[128 * BST];
    __shared__ __align__(16) unsigned Bs[128 * BST];

    const int tid  = threadIdx.x;
    const int lane = tid & 31;
    const int wid  = tid >> 5;
    const int wm0  = (wid >> 1) << 5;
    const int wn0  = (wid & 1) << 6;

    const int bm = blockIdx.y << 7;
    const int bn = blockIdx.x << 7;
    const int kbeg = blockIdx.z * kPerSplit;
    const int kend = kbeg + kPerSplit;
    C += (size_t)blockIdx.z * (size_t)M * (size_t)ldc;

    float acc[2][8][4];
#pragma unroll
    for (int mt = 0; mt < 2; ++mt)
#pragma unroll
        for (int nt = 0; nt < 8; ++nt)
#pragma unroll
            for (int r = 0; r < 4; ++r) acc[mt][nt][r] = 0.f;

    int a_off[2], b_off[4];
#pragma unroll
    for (int mt = 0; mt < 2; ++mt) {
        int row = wm0 + mt * 16 + ((lane >> 3) & 1) * 8 + (lane & 7);
        int col = (lane >> 4) * 4;
        a_off[mt] = row * BST + col;
    }
#pragma unroll
    for (int bt = 0; bt < 4; ++bt) {
        int row = wn0 + bt * 16 + (lane >> 4) * 8 + (lane & 7);
        int col = ((lane >> 3) & 1) * 4;
        b_off[bt] = row * BST + col;
    }
    const unsigned as_base = smem_u32(As);
    const unsigned bs_base = smem_u32(Bs);

    const int lrow = tid >> 3;
    const int lc4  = (tid & 7) << 2;

    for (int k0 = kbeg; k0 < kend; k0 += BK) {
#pragma unroll
        for (int i = 0; i < 4; ++i) {
            int r = lrow + (i << 5);
            float4 va = *reinterpret_cast<const float4*>(
                A + (size_t)(bm + r) * lda + k0 + lc4);
            unsigned* pa = &As[r * BST + lc4];
            pa[0] = f2tf32(va.x); pa[1] = f2tf32(va.y);
            pa[2] = f2tf32(va.z); pa[3] = f2tf32(va.w);
            float4 vb = make_float4(0.f, 0.f, 0.f, 0.f);
            if (bn + r < N)
                vb = *reinterpret_cast<const float4*>(
                    B + (size_t)(bn + r) * ldb + k0 + lc4);
            unsigned* pb = &Bs[r * BST + lc4];
            pb[0] = f2tf32(vb.x); pb[1] = f2tf32(vb.y);
            pb[2] = f2tf32(vb.z); pb[3] = f2tf32(vb.w);
        }
        __syncthreads();

#pragma unroll
        for (int kk = 0; kk < BK; kk += 8) {
            unsigned a[2][4], b[4][4];
#pragma unroll
            for (int mt = 0; mt < 2; ++mt) {
                unsigned addr = as_base + (unsigned)((a_off[mt] + kk) << 2);
                asm volatile(
                    "ldmatrix.sync.aligned.m8n8.x4.shared.b16 {%0,%1,%2,%3}, [%4];"
                    : "=r"(a[mt][0]), "=r"(a[mt][1]), "=r"(a[mt][2]), "=r"(a[mt][3])
                    : "r"(addr));
            }
#pragma unroll
            for (int bt = 0; bt < 4; ++bt) {
                unsigned addr = bs_base + (unsigned)((b_off[bt] + kk) << 2);
                asm volatile(
                    "ldmatrix.sync.aligned.m8n8.x4.shared.b16 {%0,%1,%2,%3}, [%4];"
                    : "=r"(b[bt][0]), "=r"(b[bt][1]), "=r"(b[bt][2]), "=r"(b[bt][3])
                    : "r"(addr));
            }
#pragma unroll
            for (int mt = 0; mt < 2; ++mt)
#pragma unroll
                for (int nt = 0; nt < 8; ++nt) {
                    unsigned b0 = b[nt >> 1][(nt & 1) * 2 + 0];
                    unsigned b1 = b[nt >> 1][(nt & 1) * 2 + 1];
                    asm volatile(
                        "mma.sync.aligned.m16n8k8.row.col.f32.tf32.tf32.f32 "
                        "{%0,%1,%2,%3}, {%4,%5,%6,%7}, {%8,%9}, {%0,%1,%2,%3};"
                        : "+f"(acc[mt][nt][0]), "+f"(acc[mt][nt][1]),
                          "+f"(acc[mt][nt][2]), "+f"(acc[mt][nt][3])
                        : "r"(a[mt][0]), "r"(a[mt][1]), "r"(a[mt][2]), "r"(a[mt][3]),
                          "r"(b0), "r"(b1));
                }
        }
        __syncthreads();
    }

    const int gid = lane >> 2;
    const int tig = lane & 3;
#pragma unroll
    for (int mt = 0; mt < 2; ++mt)
#pragma unroll
        for (int nt = 0; nt < 8; ++nt) {
            int m = bm + wm0 + mt * 16 + gid;
            int n = bn + wn0 + nt * 8 + tig * 2;
            if (n < N) {
                float v0 = acc[mt][nt][0], v1 = acc[mt][nt][1];
                float v2 = acc[mt][nt][2], v3 = acc[mt][nt][3];
                if (epi == 1) {
                    float b0v = bias[n], b1v = bias[n + 1];
                    v0 = softplusf(v0 + b0v); v1 = softplusf(v1 + b1v);
                    v2 = softplusf(v2 + b0v); v3 = softplusf(v3 + b1v);
                }
                *reinterpret_cast<float2*>(C + (size_t)m * ldc + n) =
                    make_float2(v0, v1);
                *reinterpret_cast<float2*>(C + (size_t)(m + 8) * ldc + n) =
                    make_float2(v2, v3);
            }
        }
}

// ---------------------------------------------------------------------------
__global__ __launch_bounds__(256)
void conv_silu_k(const float* __restrict__ xz, const float* __restrict__ w,
                 const float* __restrict__ cb, float* __restrict__ uc)
{
    int idx = blockIdx.x * blockDim.x + threadIdx.x;
    if (idx >= NROWS * DINNER) return;
    int d   = idx & (DINNER - 1);
    int row = idx >> 11;
    int l   = row & (L_SEQ - 1);
    int b   = row >> 11;

    const float4 wv = *reinterpret_cast<const float4*>(w + (size_t)d * 4);
    const float* up = xz + (size_t)b * L_SEQ * (2 * DINNER) + d;
    const size_t S = 2 * DINNER;

    float acc = cb[d] + wv.w * up[(size_t)l * S];
    if (l >= 1) acc += wv.z * up[(size_t)(l - 1) * S];
    if (l >= 2) acc += wv.y * up[(size_t)(l - 2) * S];
    if (l >= 3) acc += wv.x * up[(size_t)(l - 3) * S];

    uc[idx] = acc / (1.f + __expf(-acc));
}

__global__ void reduce_split(const float* __restrict__ part,
                             float* __restrict__ out, int n)
{
    int i = blockIdx.x * blockDim.x + threadIdx.x;
    if (i < n) {
        float s = 0.f;
#pragma unroll
        for (int z = 0; z < KSPLIT; ++z) s += part[(size_t)z * n + i];
        out[i] = s;
    }
}

// ---------------------------------------------------------------------------
// Chunked selective scan.
// Phase 1: each (b, chunk, d) scans its 128 steps from h=0; emits h_partial[16]
//          and sumDelta (since prod(exp(delta_t*A_s)) = exp(A_s * sum delta_t)).
// Combine: per (b,d), fold 16 chunk summaries sequentially -> h_init per chunk.
// Phase 3: re-scan each chunk from its h_init; fused skip + silu(z) gate.
// ---------------------------------------------------------------------------
__global__ __launch_bounds__(256)
void scan_p1(const float* __restrict__ delta, const float* __restrict__ xdbl,
             const float* __restrict__ uc, const float* __restrict__ A_log,
             float* __restrict__ hfin, float* __restrict__ sumd)
{
    const int b = blockIdx.z;
    const int c = blockIdx.y;
    const int d = blockIdx.x * 256 + threadIdx.x;

    float na[DSTATE];
#pragma unroll
    for (int s = 0; s < DSTATE; ++s)
        na[s] = -__expf(A_log[(size_t)d * DSTATE + s]);

    float h[DSTATE];
#pragma unroll
    for (int s = 0; s < DSTATE; ++s) h[s] = 0.f;
    float sd = 0.f;

    __shared__ float bs[32][DSTATE];

    const int lbeg = c * CHUNK;
    for (int l0 = lbeg; l0 < lbeg + CHUNK; l0 += 32) {
        __syncthreads();
        for (int t = threadIdx.x; t < 32 * DSTATE; t += 256) {
            int i = t >> 4, j = t & 15;
            bs[i][j] = xdbl[(size_t)(b * L_SEQ + l0 + i) * XPROJ_N + 64 + j];
        }
        __syncthreads();
#pragma unroll 4
        for (int i = 0; i < 32; ++i) {
            size_t row = (size_t)b * L_SEQ + l0 + i;
            float t  = delta[row * DINNER + d];
            float u  = uc[row * DINNER + d];
            float tu = t * u;
            sd += t;
#pragma unroll
            for (int s = 0; s < DSTATE; ++s) {
                float dA = __expf(t * na[s]);
                h[s] = fmaf(dA, h[s], tu * bs[i][s]);
            }
        }
    }

    const size_t base = ((size_t)(b * NCHUNK + c) * DSTATE) * DINNER + d;
#pragma unroll
    for (int s = 0; s < DSTATE; ++s)
        hfin[base + (size_t)s * DINNER] = h[s];
    sumd[(size_t)(b * NCHUNK + c) * DINNER + d] = sd;
}

__global__ __launch_bounds__(256)
void scan_combine(const float* __restrict__ hfin, const float* __restrict__ sumd,
                  const float* __restrict__ A_log, float* __restrict__ hini)
{
    const int b = blockIdx.y;
    const int d = blockIdx.x * 256 + threadIdx.x;

    float na[DSTATE];
#pragma unroll
    for (int s = 0; s < DSTATE; ++s)
        na[s] = -__expf(A_log[(size_t)d * DSTATE + s]);

    float h[DSTATE];
#pragma unroll
    for (int s = 0; s < DSTATE; ++s) h[s] = 0.f;

    for (int c = 0; c < NCHUNK; ++c) {
        const size_t base = ((size_t)(b * NCHUNK + c) * DSTATE) * DINNER + d;
#pragma unroll
        for (int s = 0; s < DSTATE; ++s)
            hini[base + (size_t)s * DINNER] = h[s];
        float sd = sumd[(size_t)(b * NCHUNK + c) * DINNER + d];
#pragma unroll
        for (int s = 0; s < DSTATE; ++s) {
            float pA = __expf(sd * na[s]);
            h[s] = fmaf(pA, h[s], hfin[base + (size_t)s * DINNER]);
        }
    }
}

__global__ __launch_bounds__(256)
void scan_p3(const float* __restrict__ delta, const float* __restrict__ xdbl,
             const float* __restrict__ uc, const float* __restrict__ xz,
             const float* __restrict__ A_log, const float* __restrict__ Dv,
             const float* __restrict__ hini, float* __restrict__ y)
{
    const int b = blockIdx.z;
    const int c = blockIdx.y;
    const int d = blockIdx.x * 256 + threadIdx.x;

    float na[DSTATE];
#pragma unroll
    for (int s = 0; s < DSTATE; ++s)
        na[s] = -__expf(A_log[(size_t)d * DSTATE + s]);

    float h[DSTATE];
    {
        const size_t base = ((size_t)(b * NCHUNK + c) * DSTATE) * DINNER + d;
#pragma unroll
        for (int s = 0; s < DSTATE; ++s)
            h[s] = hini[base + (size_t)s * DINNER];
    }

    const float Dd = Dv[d];
    __shared__ float bc[32][32];   // [step][B(16) | C(16)]

    const int lbeg = c * CHUNK;
    for (int l0 = lbeg; l0 < lbeg + CHUNK; l0 += 32) {
        __syncthreads();
        for (int t = threadIdx.x; t < 1024; t += 256) {
            int i = t >> 5, j = t & 31;
            bc[i][j] = xdbl[(size_t)(b * L_SEQ + l0 + i) * XPROJ_N + 64 + j];
        }
        __syncthreads();
#pragma unroll 4
        for (int i = 0; i < 32; ++i) {
            size_t row = (size_t)b * L_SEQ + l0 + i;
            float t  = delta[row * DINNER + d];
            float u  = uc[row * DINNER + d];
            float tu = t * u;
            float yv = 0.f;
#pragma unroll
            for (int s = 0; s < DSTATE; ++s) {
                float dA = __expf(t * na[s]);
                h[s] = fmaf(dA, h[s], tu * bc[i][s]);
                yv   = fmaf(h[s], bc[i][16 + s], yv);
            }
            float zv = xz[row * (2 * DINNER) + DINNER + d];
            float g  = zv / (1.f + __expf(-zv));
            y[row * DINNER + d] = (yv + u * Dd) * g;
        }
    }
}

// ---------------------------------------------------------------------------
extern "C" void kernel_launch(void* const* d_in, const int* in_sizes, int n_in,
                              void* d_out, int out_size)
{
    const float* x        = (const float*)d_in[0];
    const float* W_in     = (const float*)d_in[1];
    const float* conv_w   = (const float*)d_in[2];
    const float* conv_b   = (const float*)d_in[3];
    const float* W_xproj  = (const float*)d_in[4];
    const float* W_dtproj = (const float*)d_in[5];
    const float* dt_bias  = (const float*)d_in[6];
    const float* A_log    = (const float*)d_in[7];
    const float* Dv       = (const float*)d_in[8];
    const float* W_out    = (const float*)d_in[9];
    float* out = (float*)d_out;

    float *xz, *uc, *xpart, *xdbl, *delta, *y, *hfin, *hini, *sumd;
    cudaGetSymbolAddress((void**)&xz,    g_xz);
    cudaGetSymbolAddress((void**)&uc,    g_uc);
    cudaGetSymbolAddress((void**)&xpart, g_xpart);
    cudaGetSymbolAddress((void**)&xdbl,  g_xdbl);
    cudaGetSymbolAddress((void**)&delta, g_delta);
    cudaGetSymbolAddress((void**)&y,     g_y);
    cudaGetSymbolAddress((void**)&hfin,  g_hfin);
    cudaGetSymbolAddress((void**)&hini,  g_hini);
    cudaGetSymbolAddress((void**)&sumd,  g_sumd);

    dim3 blk(256);

    // 1. in_proj: xz[4096,4096] = x @ W_in^T  (K=1024)
    mma_tn<<<dim3(32, 32, 1), blk>>>(x, W_in, xz,
        NROWS, 2 * DINNER, DMODEL, DMODEL, DMODEL, 2 * DINNER,
        nullptr, 0, DMODEL);

    // 2. depthwise conv + silu
    conv_silu_k<<<(NROWS * DINNER) / 256, blk>>>(xz, conv_w, conv_b, uc);

    // 3. x_proj (split-K x8): x_dbl[4096,96] = u_c @ W_xproj^T (K=2048)
    mma_tn<<<dim3(1, 32, KSPLIT), blk>>>(uc, W_xproj, xpart,
        NROWS, XPROJ_N, DINNER, DINNER, DINNER, XPROJ_N,
        nullptr, 0, DINNER / KSPLIT);
    reduce_split<<<(NROWS * XPROJ_N + 255) / 256, blk>>>(
        xpart, xdbl, NROWS * XPROJ_N);

    // 4. dt_proj + softplus: delta[4096,2048] (K=64)
    mma_tn<<<dim3(16, 32, 1), blk>>>(xdbl, W_dtproj, delta,
        NROWS, DINNER, 64, XPROJ_N, 64, DINNER,
        dt_bias, 1, 64);

    // 5. chunked selective scan + skip + gate
    scan_p1<<<dim3(DINNER / 256, NCHUNK, NB), blk>>>(
        delta, xdbl, uc, A_log, hfin, sumd);
    scan_combine<<<dim3(DINNER / 256, NB), blk>>>(hfin, sumd, A_log, hini);
    scan_p3<<<dim3(DINNER / 256, NCHUNK, NB), blk>>>(
        delta, xdbl, uc, xz, A_log, Dv, hini, y);

    // 6. out_proj: out[4096,1024] = y @ W_out^T (K=2048)
    mma_tn<<<dim3(8, 32, 1), blk>>>(y, W_out, out,
        NROWS, DMODEL, DINNER, DINNER, DINNER, DMODEL,
        nullptr, 0, DINNER);
}